// round 9
// baseline (speedup 1.0000x reference)
#include <cuda_runtime.h>
#include <math.h>

#define B 8
#define L 2048
#define NT 21          // num types incl. padding idx 0
#define DTY 32
#define DH 544         // 512 + 32
#define THREADS 256
#define NTILES (B * (L / 2))   // 8192 mirror-pair tiles
#define NBLK 912               // ~6 resident blocks per SM, persistent

// ---------------------------------------------------------------------------
// Persistent fused kernel. Tile q of batch b owns the mirror row pair
// (i = q, m = L-1-q): together exactly L-1 lower-triangle elements, so every
// tile costs the same. Block p statically owns tiles [p*NTILES/NBLK,
// (p+1)*NTILES/NBLK) in batch-major order: s_t/s_ty reload only on batch
// change, the 441-entry type-pair table is batch-independent and built once.
// ---------------------------------------------------------------------------
__global__ __launch_bounds__(THREADS, 6) void fused_kernel(
    const int*   __restrict__ event_type,
    const float* __restrict__ event_time,
    const float* __restrict__ Wt_pos,
    const float* __restrict__ type_emb,
    const float* __restrict__ w_l, const float* __restrict__ b_l,
    const float* __restrict__ w_g, const float* __restrict__ b_g,
    float* __restrict__ scores,
    float* __restrict__ hidden,
    float* __restrict__ tdiff) {

    __shared__ float          s_t[L];
    __shared__ unsigned char  s_ty[L];
    __shared__ float2         s_tab[NT * NT];   // {0.4*g, 1/l}
    __shared__ float          pa[NT], pb[NT], ga[NT], gb[NT];

    const int tid = threadIdx.x;

    // --- one-time: per-type dot products + 441-entry table (batch-indep) ----
    if (tid < NT) {
        float sa = 0.f, sb = 0.f, sga = 0.f, sgb = 0.f;
#pragma unroll
        for (int k = 0; k < DTY; k++) {
            float e = type_emb[tid * DTY + k];
            sa  = fmaf(e, w_l[k],       sa);
            sb  = fmaf(e, w_l[DTY + k], sb);
            sga = fmaf(e, w_g[k],       sga);
            sgb = fmaf(e, w_g[DTY + k], sgb);
        }
        pa[tid] = sa; pb[tid] = sb; ga[tid] = sga; gb[tid] = sgb;
    }
    __syncthreads();
    {
        const float blv = b_l[0], bgv = b_g[0];
        for (int idx = tid; idx < NT * NT; idx += THREADS) {
            int ti = idx / NT;   // i-side type
            int tj = idx % NT;   // j-side type
            float xl = pa[tj] + pb[ti] + blv;
            float sp = fmaxf(xl, 0.f) + log1pf(expf(-fabsf(xl)));
            float lv = sp + 1e-6f;
            float xg = 5.0f * (ga[tj] + gb[ti] + bgv);
            float g  = 1.f / (1.f + expf(-xg));
            s_tab[idx] = make_float2(0.4f * g, 1.f / lv);
        }
    }

    // per-thread hidden constants
    const float c   = (float)(-9.210340371976184 / 512.0); // -ln(10000)/d_model
    const float div = expf((float)(2 * tid) * c);
    const float wt  = Wt_pos[tid];

    const int p  = blockIdx.x;
    const int t0 = (int)(((long long)p       * NTILES) / NBLK);
    const int t1 = (int)(((long long)(p + 1) * NTILES) / NBLK);
    int cur_b = -1;

    for (int t = t0; t < t1; ++t) {
        const int b = t >> 10;          // t / (L/2)
        const int q = t & 1023;         // t % (L/2)
        if (b != cur_b) {
            __syncthreads();            // retire reads of previous batch rows
            for (int j = tid; j < L; j += THREADS) {
                s_t[j]  = event_time[b * L + j];
                s_ty[j] = (unsigned char)event_type[b * L + j];
            }
            __syncthreads();
            cur_b = b;
        }

        const int i = q;
        const int m = L - 1 - q;

        // --- hidden rows i and m ---------------------------------------------
        {
            float s, cth;
            float* basei = hidden + ((size_t)(cur_b * L + i)) * DH;
            sincosf((float)i * div + s_t[i] * wt, &s, &cth);
            __stcs(basei + tid,       s);
            __stcs(basei + 256 + tid, cth);
            float* basem = hidden + ((size_t)(cur_b * L + m)) * DH;
            sincosf((float)m * div + s_t[m] * wt, &s, &cth);
            __stcs(basem + tid,       s);
            __stcs(basem + 256 + tid, cth);
            if (tid < 64) {
                int row = tid >> 5;     // 0 -> i, 1 -> m
                int col = tid & 31;
                int r   = row ? m : i;
                int ty  = (int)s_ty[r];
                __stcs(hidden + ((size_t)(cur_b * L + r)) * DH + 512 + col,
                       type_emb[ty * DTY + col]);
            }
        }

        // --- pairwise rows i and m ------------------------------------------
        const float ti  = s_t[i];
        const float tm  = s_t[m];
        const int   tbi = (int)s_ty[i] * NT;
        const int   tbm = (int)s_ty[m] * NT;
        float* sci = scores + ((size_t)(cur_b * L + i)) * L;
        float* tdi = tdiff  + ((size_t)(cur_b * L + i)) * L;
        float* scm = scores + ((size_t)(cur_b * L + m)) * L;
        float* tdm = tdiff  + ((size_t)(cur_b * L + m)) * L;

#pragma unroll
        for (int chunk = 0; chunk < 2; ++chunk) {
            const int j = chunk * (THREADS * 4) + tid * 4;
            const float4 tj  = *reinterpret_cast<const float4*>(&s_t[j]);
            const uchar4 tyv = *reinterpret_cast<const uchar4*>(&s_ty[j]);
            const int jx = tyv.x, jy = tyv.y, jz = tyv.z, jw = tyv.w;

            // row m (mostly full work)
            {
                float4 dv, sv = make_float4(0.f, 0.f, 0.f, 0.f);
                dv.x = fabsf(tm - tj.x);
                dv.y = fabsf(tm - tj.y);
                dv.z = fabsf(tm - tj.z);
                dv.w = fabsf(tm - tj.w);
                if (j < m) {
                    float2 v; float e, se, ex;
                    v = s_tab[tbm + jx]; e = dv.x * v.y;
                    se = __expf(-0.5f * e * e); ex = __expf(-e);
                    sv.x = v.x * fmaf(0.75f, ex, se);
                    v = s_tab[tbm + jy]; e = dv.y * v.y;
                    se = __expf(-0.5f * e * e); ex = __expf(-e);
                    sv.y = (j + 1 < m) ? v.x * fmaf(0.75f, ex, se) : 0.f;
                    v = s_tab[tbm + jz]; e = dv.z * v.y;
                    se = __expf(-0.5f * e * e); ex = __expf(-e);
                    sv.z = (j + 2 < m) ? v.x * fmaf(0.75f, ex, se) : 0.f;
                    v = s_tab[tbm + jw]; e = dv.w * v.y;
                    se = __expf(-0.5f * e * e); ex = __expf(-e);
                    sv.w = (j + 3 < m) ? v.x * fmaf(0.75f, ex, se) : 0.f;
                }
                __stcs(reinterpret_cast<float4*>(scm + j), sv);
                __stcs(reinterpret_cast<float4*>(tdm + j), dv);
            }
            // row i (mostly zero scores)
            {
                float4 dv, sv = make_float4(0.f, 0.f, 0.f, 0.f);
                dv.x = fabsf(ti - tj.x);
                dv.y = fabsf(ti - tj.y);
                dv.z = fabsf(ti - tj.z);
                dv.w = fabsf(ti - tj.w);
                if (j < i) {
                    float2 v; float e, se, ex;
                    v = s_tab[tbi + jx]; e = dv.x * v.y;
                    se = __expf(-0.5f * e * e); ex = __expf(-e);
                    sv.x = v.x * fmaf(0.75f, ex, se);
                    v = s_tab[tbi + jy]; e = dv.y * v.y;
                    se = __expf(-0.5f * e * e); ex = __expf(-e);
                    sv.y = (j + 1 < i) ? v.x * fmaf(0.75f, ex, se) : 0.f;
                    v = s_tab[tbi + jz]; e = dv.z * v.y;
                    se = __expf(-0.5f * e * e); ex = __expf(-e);
                    sv.z = (j + 2 < i) ? v.x * fmaf(0.75f, ex, se) : 0.f;
                    v = s_tab[tbi + jw]; e = dv.w * v.y;
                    se = __expf(-0.5f * e * e); ex = __expf(-e);
                    sv.w = (j + 3 < i) ? v.x * fmaf(0.75f, ex, se) : 0.f;
                }
                __stcs(reinterpret_cast<float4*>(sci + j), sv);
                __stcs(reinterpret_cast<float4*>(tdi + j), dv);
            }
        }
    }
}

// ---------------------------------------------------------------------------
extern "C" void kernel_launch(void* const* d_in, const int* in_sizes, int n_in,
                              void* d_out, int out_size) {
    const int*   event_type = (const int*)d_in[0];
    const float* event_time = (const float*)d_in[1];
    // d_in[2] = arrival_times (unused by reference)
    const float* Wt_pos   = (const float*)d_in[3];
    const float* type_emb = (const float*)d_in[4];
    const float* w_l      = (const float*)d_in[5];
    const float* b_l      = (const float*)d_in[6];
    const float* w_g      = (const float*)d_in[7];
    const float* b_g      = (const float*)d_in[8];

    float* out    = (float*)d_out;
    float* scores = out;                                   // [B, L, L]
    float* hidden = out + (size_t)B * L * L;               // [B, L, 544]
    float* tdiff  = hidden + (size_t)B * L * DH;           // [B, L, L]

    fused_kernel<<<NBLK, THREADS>>>(
        event_type, event_time, Wt_pos, type_emb,
        w_l, b_l, w_g, b_g, scores, hidden, tdiff);
}